// round 8
// baseline (speedup 1.0000x reference)
#include <cuda_runtime.h>
#include <cuda_fp16.h>
#include <stdint.h>

// RNNWithCheckpoint: T=512, B=128, H=1024, L=4 multi-layer tanh RNN.
// R6: R5 async per-layer pipeline + FINE-GRAINED chunk-wise dependency gates.
// Chunk c of the A operand only needs source clusters 2c,2c+1 (4 CTAs), so
// each fill is gated on 4 flags instead of a whole-layer 32-CTA convergence.
// In-loop gates pre-issue flag loads and check after the MMA block (hidden).
// WAR gate moved to epilogue, loads hidden under the cluster barrier.

#define T_STEPS 512
#define BATCH   128
#define HID     1024
#define LAYERS  4
#define NCTA    128

#define WROW 1032          // 1024 + 8 halves (bank-shift pad)
#define AROW 136           // 128 + 8 halves
#define SM_W  0            // 64 x WROW halves  = 132096 B
#define SM_A0 132096       // 128 x AROW halves = 34816 B
#define SM_A1 166912
#define SM_P  201728       // partial 64 x 68 fp32 = 17408 B (dedicated)
#define SMEM_BYTES 219136

// Static device scratch (no cudaMalloc allowed)
__device__ __align__(16) __half g_Wh[LAYERS * 2 * HID * HID];   // [l][ks][n][k]
__device__ __align__(16) __half g_xh[(size_t)T_STEPS * BATCH * HID];
__device__ __align__(16) float  g_bias[LAYERS * HID];
__device__ __align__(16) __half g_act[2][LAYERS * BATCH * HID]; // slot = t&1
__device__ unsigned g_flags[NCTA * 32];   // F[cta] = completed steps, 128B stride

// ------------------------------------------------------------- helpers ----
__device__ __forceinline__ uint32_t smem_u32(const void* p) {
    uint32_t a;
    asm("{ .reg .u64 t; cvta.to.shared.u64 t, %1; cvt.u32.u64 %0, t; }"
        : "=r"(a) : "l"(p));
    return a;
}
__device__ __forceinline__ void cp16(uint32_t dst, const void* src) {
    asm volatile("cp.async.cg.shared.global [%0], [%1], 16;"
                 :: "r"(dst), "l"(src) : "memory");
}
__device__ __forceinline__ void ldsm4(uint32_t* r, uint32_t a) {
    asm volatile("ldmatrix.sync.aligned.m8n8.x4.shared.b16 {%0,%1,%2,%3}, [%4];"
                 : "=r"(r[0]), "=r"(r[1]), "=r"(r[2]), "=r"(r[3]) : "r"(a));
}
__device__ __forceinline__ void mma16816(float* c, const uint32_t* a,
                                         uint32_t b0, uint32_t b1) {
    asm volatile(
        "mma.sync.aligned.m16n8k16.row.col.f32.f16.f16.f32 "
        "{%0,%1,%2,%3}, {%4,%5,%6,%7}, {%8,%9}, {%0,%1,%2,%3};"
        : "+f"(c[0]), "+f"(c[1]), "+f"(c[2]), "+f"(c[3])
        : "r"(a[0]), "r"(a[1]), "r"(a[2]), "r"(a[3]), "r"(b0), "r"(b1));
}
__device__ __forceinline__ uint32_t mapa_u32(uint32_t a, uint32_t rk) {
    uint32_t o;
    asm("mapa.shared::cluster.u32 %0, %1, %2;" : "=r"(o) : "r"(a), "r"(rk));
    return o;
}
__device__ __forceinline__ void st_dsmem2(uint32_t a, float x, float y) {
    asm volatile("st.shared::cluster.v2.f32 [%0], {%1,%2};"
                 :: "r"(a), "f"(x), "f"(y) : "memory");
}
__device__ __forceinline__ unsigned ldflag(int cta) {
    unsigned v;
    asm volatile("ld.global.cg.u32 %0, [%1];"
                 : "=r"(v) : "l"(g_flags + (size_t)cta * 32) : "memory");
    return v;
}
// Blocking poll: lanes [0,nl) watch flags[base+lane] >= tgt.
__device__ __forceinline__ void pollN(int base, unsigned tgt, int lane, int nl)
{
    bool ok = (lane < nl) ? (ldflag(base + lane) >= tgt) : true;
    while (!__all_sync(0xffffffffu, ok)) {
        __nanosleep(30);
        if (lane < nl) ok = (ldflag(base + lane) >= tgt);
    }
}

// ---------------------------------------------------------------- prep ----
__global__ void __launch_bounds__(256) prep_kernel(
    const float* __restrict__ x,
    const float* __restrict__ Wih, const float* __restrict__ Whh,
    const float* __restrict__ bih, const float* __restrict__ bhh)
{
    int tid  = blockIdx.x * blockDim.x + threadIdx.x;
    int nthr = gridDim.x * blockDim.x;
    const int NW = LAYERS * HID * HID;
    for (int i = tid; i < NW; i += nthr) {
        int l  = i >> 20;
        int nk = i & (HID * HID - 1);
        g_Wh[((size_t)(l * 2 + 0) << 20) + nk] = __float2half(Wih[i]);
        g_Wh[((size_t)(l * 2 + 1) << 20) + nk] = __float2half(Whh[i]);
    }
    const size_t NX4 = (size_t)T_STEPS * BATCH * HID / 4;
    for (size_t i = tid; i < NX4; i += nthr) {
        float4 v = *(const float4*)(x + i * 4);
        *(__half2*)&g_xh[i * 4]     = __floats2half2_rn(v.x, v.y);
        *(__half2*)&g_xh[i * 4 + 2] = __floats2half2_rn(v.z, v.w);
    }
    for (int i = tid; i < LAYERS * HID; i += nthr) g_bias[i] = bih[i] + bhh[i];
    for (int i = tid; i < LAYERS * BATCH * HID; i += nthr) {
        g_act[0][i] = __float2half(0.0f);
        g_act[1][i] = __float2half(0.0f);
    }
    for (int i = tid; i < NCTA * 32; i += nthr) g_flags[i] = 0;
}

// ----------------------------------------------------------- persistent ---
// bx: l = bx>>5, nt = (bx>>1)&15, rank = bx&1 (cluster pair = the 2 k-halves).
__global__ void __launch_bounds__(256) __cluster_dims__(2, 1, 1)
rnn_persistent(float* __restrict__ out)
{
    extern __shared__ char sh[];
    const uint32_t sb = smem_u32(sh);

    const int bx   = blockIdx.x;
    const int l    = bx >> 5;
    const int nt   = (bx >> 1) & 15;
    const int rank = bx & 1;
    const int tid  = threadIdx.x;
    const int wid  = tid >> 5, lane = tid & 31;
    const int g    = lane >> 2, tq = lane & 3;
    const int wm   = (wid >> 1) * 32;   // 4 m-groups of 32 rows
    const int wn   = (wid & 1) * 32;    // 2 n-groups of 32 cols

    // ---- resident weight slice: 64 n-rows x 1024 k halves
    {
        const __half* wsrc = g_Wh + (((size_t)(l * 2 + rank) * HID) + nt * 64) * HID;
        for (int i = tid; i < 8192; i += 256) {
            int r = i >> 7, c = i & 127;
            cp16(sb + SM_W + (uint32_t)(r * WROW + c * 8) * 2,
                 wsrc + (size_t)r * HID + c * 8);
        }
        asm volatile("cp.async.commit_group;" ::: "memory");
        asm volatile("cp.async.wait_group 0;" ::: "memory");
        __syncthreads();
    }

    // per-thread constant addresses
    const uint32_t aoff = (uint32_t)(((wm + (lane & 15)) * AROW + (lane >> 4) * 8) * 2);
    uint32_t wb[2];
    #pragma unroll
    for (int p = 0; p < 2; p++)
        wb[p] = sb + SM_W +
                (uint32_t)(((wn + p * 16 + (lane & 15)) * WROW + (lane >> 4) * 8) * 2);
    float2 bs[4];
    #pragma unroll
    for (int nti = 0; nti < 4; nti++)
        bs[nti] = *(const float2*)&g_bias[l * HID + nt * 64 + wn + nti * 8 + tq * 2];

    const int  fin0    = rank * 64;      // rows this CTA finalizes
    const int  nonfin0 = 64 - fin0;      // rows pushed to peer (= peer fin0)
    const bool fin_w   = (rank == 0) ? (wm < 64) : (wm >= 64);
    float* sP = (float*)(sh + SM_P);
    const uint32_t peer_sp = mapa_u32(sb + SM_P, (uint32_t)(rank ^ 1));

    // fine-grained gate parameters (constant across steps except target)
    const bool gated = (rank == 1) || (l > 0);
    const int  gbase = (rank == 1) ? l * 32 : (l - 1) * 32;  // + 4*chunk
    const int  dbase = (l + 1) * 32;                         // WAR: downstream

    #pragma unroll 1
    for (int t = 0; t < T_STEPS; t++) {
        const unsigned gtgt = (rank == 1) ? (unsigned)t : (unsigned)(t + 1);

        // A source: rank0 = layer input h[l-1][t] (slot t&1) or x;
        //           rank1 = own h[l][t-1] (slot (t&1)^1)
        const __half* src;
        if (rank == 1)   src = g_act[(t & 1) ^ 1] + (size_t)l * BATCH * HID;
        else if (l == 0) src = g_xh + (size_t)t * BATCH * HID;
        else             src = g_act[t & 1] + (size_t)(l - 1) * BATCH * HID;

        // ---- prologue: gate chunks 0,1 (8 flags), then fill both ----
        if (gated && gtgt > 0) pollN(gbase, gtgt, lane, 8);
        #pragma unroll
        for (int c0 = 0; c0 < 2; c0++) {
            uint32_t dst = sb + (c0 ? SM_A1 : SM_A0);
            const __half* sp = src + c0 * 128;
            for (int i = tid; i < 2048; i += 256) {
                int r = i >> 4, c = i & 15;
                cp16(dst + (uint32_t)(r * AROW + c * 8) * 2,
                     sp + (size_t)r * HID + c * 8);
            }
            asm volatile("cp.async.commit_group;" ::: "memory");
        }

        float acc[2][4][4];
        #pragma unroll
        for (int i = 0; i < 2; i++)
            #pragma unroll
            for (int j = 0; j < 4; j++)
                #pragma unroll
                for (int k = 0; k < 4; k++) acc[i][j][k] = 0.0f;

        #pragma unroll 2
        for (int ch = 0; ch < 8; ch++) {
            if (ch < 7) asm volatile("cp.async.wait_group 1;" ::: "memory");
            else        asm volatile("cp.async.wait_group 0;" ::: "memory");
            __syncthreads();

            // pre-issue refill-gate flag loads (checked after MMA, hidden)
            const bool need = gated && gtgt > 0 && ch < 6;
            unsigned pf = 0xffffffffu;
            if (need && lane < 4) pf = ldflag(gbase + 4 * (ch + 2) + lane);

            uint32_t ab = sb + ((ch & 1) ? SM_A1 : SM_A0) + aoff;
            uint32_t kb = (uint32_t)(ch * 256);
            #pragma unroll
            for (int j = 0; j < 8; j++) {
                uint32_t a0[4], a1[4], b0[4], b1[4];
                ldsm4(a0, ab + j * 32);
                ldsm4(a1, ab + 16 * AROW * 2 + j * 32);
                ldsm4(b0, wb[0] + kb + j * 32);
                ldsm4(b1, wb[1] + kb + j * 32);
                mma16816(acc[0][0], a0, b0[0], b0[2]);
                mma16816(acc[0][1], a0, b0[1], b0[3]);
                mma16816(acc[0][2], a0, b1[0], b1[2]);
                mma16816(acc[0][3], a0, b1[1], b1[3]);
                mma16816(acc[1][0], a1, b0[0], b0[2]);
                mma16816(acc[1][1], a1, b0[1], b0[3]);
                mma16816(acc[1][2], a1, b1[0], b1[2]);
                mma16816(acc[1][3], a1, b1[1], b1[3]);
            }
            __syncthreads();
            if (ch < 6) {   // refill this buffer with chunk ch+2 (gated)
                if (need) {
                    bool ok = (lane < 4) ? (pf >= gtgt) : true;
                    while (!__all_sync(0xffffffffu, ok)) {
                        __nanosleep(30);
                        if (lane < 4) ok = (ldflag(gbase + 4 * (ch + 2) + lane) >= gtgt);
                    }
                }
                uint32_t dst = sb + ((ch & 1) ? SM_A1 : SM_A0);
                const __half* sp = src + (ch + 2) * 128;
                for (int i = tid; i < 2048; i += 256) {
                    int r = i >> 4, c = i & 15;
                    cp16(dst + (uint32_t)(r * AROW + c * 8) * 2,
                         sp + (size_t)r * HID + c * 8);
                }
                asm volatile("cp.async.commit_group;" ::: "memory");
            }
        }

        // ---- PUSH partial rows to peer's sP (remote write, latency hidden)
        if (!fin_w) {
            #pragma unroll
            for (int mt = 0; mt < 2; mt++) {
                int rr = wm + mt * 16 + g - nonfin0;   // index in peer's fin range
                #pragma unroll
                for (int nti = 0; nti < 4; nti++) {
                    int c = wn + nti * 8 + tq * 2;
                    st_dsmem2(peer_sp + (uint32_t)(rr * 68 + c) * 4,
                              acc[mt][nti][0], acc[mt][nti][1]);
                    st_dsmem2(peer_sp + (uint32_t)((rr + 8) * 68 + c) * 4,
                              acc[mt][nti][2], acc[mt][nti][3]);
                }
            }
        }
        // pre-issue WAR-gate flag loads (checked after barrier, hidden)
        const bool war = (l < 3) && (t >= 2);
        unsigned wf = 0xffffffffu;
        if (war && fin_w) wf = ldflag(dbase + lane);

        asm volatile("barrier.cluster.arrive.aligned;" ::: "memory");
        asm volatile("barrier.cluster.wait.aligned;" ::: "memory");

        // ---- finalize: local sP read + bias + tanh -> act slot t&1 (+ out)
        if (fin_w) {
            if (war) {
                unsigned wt = (unsigned)(t - 1);
                bool ok = (wf >= wt);
                while (!__all_sync(0xffffffffu, ok)) {
                    __nanosleep(30);
                    ok = (ldflag(dbase + lane) >= wt);
                }
            }
            __half* actw = g_act[t & 1] + (size_t)l * BATCH * HID;
            #pragma unroll
            for (int mt = 0; mt < 2; mt++) {
                int rg = wm + mt * 16 + g;
                int rr = rg - fin0;
                #pragma unroll
                for (int nti = 0; nti < 4; nti++) {
                    int c = wn + nti * 8 + tq * 2;
                    float2 p0 = *(const float2*)&sP[rr * 68 + c];
                    float2 p1 = *(const float2*)&sP[(rr + 8) * 68 + c];
                    float v0 = tanhf(acc[mt][nti][0] + p0.x + bs[nti].x);
                    float v1 = tanhf(acc[mt][nti][1] + p0.y + bs[nti].y);
                    float v2 = tanhf(acc[mt][nti][2] + p1.x + bs[nti].x);
                    float v3 = tanhf(acc[mt][nti][3] + p1.y + bs[nti].y);
                    int cn = nt * 64 + c;
                    *(__half2*)&actw[(size_t)rg * HID + cn] =
                        __floats2half2_rn(v0, v1);
                    *(__half2*)&actw[(size_t)(rg + 8) * HID + cn] =
                        __floats2half2_rn(v2, v3);
                    if (l == 3) {
                        float* ob = out + (size_t)t * BATCH * HID + cn;
                        *(float2*)&ob[(size_t)rg * HID] = make_float2(v0, v1);
                        *(float2*)&ob[(size_t)(rg + 8) * HID] = make_float2(v2, v3);
                    }
                }
            }
        }

        // ---- publish progress ----
        __syncthreads();
        if (tid == 0) {
            __threadfence();
            atomicExch(&g_flags[bx * 32], (unsigned)(t + 1));
        }
    }
}

// -------------------------------------------------------------- launch ----
extern "C" void kernel_launch(void* const* d_in, const int* in_sizes, int n_in,
                              void* d_out, int out_size)
{
    const float* x   = (const float*)d_in[0];
    const float* Wih = (const float*)d_in[1];
    const float* Whh = (const float*)d_in[2];
    const float* bih = (const float*)d_in[3];
    const float* bhh = (const float*)d_in[4];
    float* out = (float*)d_out;

    cudaFuncSetAttribute(rnn_persistent,
                         cudaFuncAttributeMaxDynamicSharedMemorySize, SMEM_BYTES);

    prep_kernel<<<2048, 256>>>(x, Wih, Whh, bih, bhh);
    rnn_persistent<<<NCTA, 256, SMEM_BYTES>>>(out);
}

// round 9
// speedup vs baseline: 1.0529x; 1.0529x over previous
#include <cuda_runtime.h>
#include <cuda_fp16.h>
#include <stdint.h>

// RNNWithCheckpoint: T=512, B=128, H=1024, L=4 multi-layer tanh RNN.
// R7: R5 async layer pipeline + restructured mainloop:
//   - 16 chunks x 64 cols, 3 XOR-swizzled A buffers, ONE syncthreads/chunk,
//     refill issued before compute (distance-2).
//   - fully strength-reduced fill + ldsm addressing (precomputed swizzle).
// 128 CTAs = 4 layers x 16 n-tiles(64) x 2 k-ranks (ih|hh); DSMEM push reduce.

#define T_STEPS 512
#define BATCH   128
#define HID     1024
#define LAYERS  4
#define NCTA    128

#define SM_W   0            // 64 rows x 2048B, XOR-swizzled = 131072
#define SM_AB  131072       // 3 A bufs, each 128 rows x 128B = 16384
#define ABUF   16384
#define SM_P   180224       // partial 64 x 68 fp32 = 17408
#define SMEM_BYTES 197632

// Static device scratch (no cudaMalloc allowed)
__device__ __align__(16) __half g_Wh[LAYERS * 2 * HID * HID];   // [l][ks][n][k]
__device__ __align__(16) __half g_xh[(size_t)T_STEPS * BATCH * HID];
__device__ __align__(16) float  g_bias[LAYERS * HID];
__device__ __align__(16) __half g_act[2][LAYERS * BATCH * HID]; // slot = t&1
__device__ unsigned g_flags[NCTA * 32];   // F[cta] = completed steps

// ------------------------------------------------------------- helpers ----
__device__ __forceinline__ uint32_t smem_u32(const void* p) {
    uint32_t a;
    asm("{ .reg .u64 t; cvta.to.shared.u64 t, %1; cvt.u32.u64 %0, t; }"
        : "=r"(a) : "l"(p));
    return a;
}
__device__ __forceinline__ void cp16(uint32_t dst, const void* src) {
    asm volatile("cp.async.cg.shared.global [%0], [%1], 16;"
                 :: "r"(dst), "l"(src) : "memory");
}
__device__ __forceinline__ void ldsm4(uint32_t* r, uint32_t a) {
    asm volatile("ldmatrix.sync.aligned.m8n8.x4.shared.b16 {%0,%1,%2,%3}, [%4];"
                 : "=r"(r[0]), "=r"(r[1]), "=r"(r[2]), "=r"(r[3]) : "r"(a));
}
__device__ __forceinline__ void mma16816(float* c, const uint32_t* a,
                                         uint32_t b0, uint32_t b1) {
    asm volatile(
        "mma.sync.aligned.m16n8k16.row.col.f32.f16.f16.f32 "
        "{%0,%1,%2,%3}, {%4,%5,%6,%7}, {%8,%9}, {%0,%1,%2,%3};"
        : "+f"(c[0]), "+f"(c[1]), "+f"(c[2]), "+f"(c[3])
        : "r"(a[0]), "r"(a[1]), "r"(a[2]), "r"(a[3]), "r"(b0), "r"(b1));
}
__device__ __forceinline__ uint32_t mapa_u32(uint32_t a, uint32_t rk) {
    uint32_t o;
    asm("mapa.shared::cluster.u32 %0, %1, %2;" : "=r"(o) : "r"(a), "r"(rk));
    return o;
}
__device__ __forceinline__ void st_dsmem2(uint32_t a, float x, float y) {
    asm volatile("st.shared::cluster.v2.f32 [%0], {%1,%2};"
                 :: "r"(a), "f"(x), "f"(y) : "memory");
}
__device__ __forceinline__ unsigned ldflag(int cta) {
    unsigned v;
    asm volatile("ld.global.cg.u32 %0, [%1];"
                 : "=r"(v) : "l"(g_flags + (size_t)cta * 32) : "memory");
    return v;
}
__device__ __forceinline__ void poll_group(int base32, int target, int lane)
{
    if (target <= 0) return;
    unsigned tgt = (unsigned)target;
    for (;;) {
        bool ok = ldflag(base32 + lane) >= tgt;
        if (__all_sync(0xffffffffu, ok)) break;
        __nanosleep(40);
    }
}

// ---------------------------------------------------------------- prep ----
__global__ void __launch_bounds__(256) prep_kernel(
    const float* __restrict__ x,
    const float* __restrict__ Wih, const float* __restrict__ Whh,
    const float* __restrict__ bih, const float* __restrict__ bhh)
{
    int tid  = blockIdx.x * blockDim.x + threadIdx.x;
    int nthr = gridDim.x * blockDim.x;
    const int NW = LAYERS * HID * HID;
    for (int i = tid; i < NW; i += nthr) {
        int l  = i >> 20;
        int nk = i & (HID * HID - 1);
        g_Wh[((size_t)(l * 2 + 0) << 20) + nk] = __float2half(Wih[i]);
        g_Wh[((size_t)(l * 2 + 1) << 20) + nk] = __float2half(Whh[i]);
    }
    const size_t NX4 = (size_t)T_STEPS * BATCH * HID / 4;
    for (size_t i = tid; i < NX4; i += nthr) {
        float4 v = *(const float4*)(x + i * 4);
        *(__half2*)&g_xh[i * 4]     = __floats2half2_rn(v.x, v.y);
        *(__half2*)&g_xh[i * 4 + 2] = __floats2half2_rn(v.z, v.w);
    }
    for (int i = tid; i < LAYERS * HID; i += nthr) g_bias[i] = bih[i] + bhh[i];
    for (int i = tid; i < LAYERS * BATCH * HID; i += nthr) {
        g_act[0][i] = __float2half(0.0f);
        g_act[1][i] = __float2half(0.0f);
    }
    for (int i = tid; i < NCTA * 32; i += nthr) g_flags[i] = 0;
}

// ----------------------------------------------------------- persistent ---
// bx: l = bx>>5, nt = (bx>>1)&15, rank = bx&1 (cluster pair = 2 k-halves).
__global__ void __launch_bounds__(256) __cluster_dims__(2, 1, 1)
rnn_persistent(float* __restrict__ out)
{
    extern __shared__ char sh[];
    const uint32_t sb = smem_u32(sh);

    const int bx   = blockIdx.x;
    const int l    = bx >> 5;
    const int nt   = (bx >> 1) & 15;
    const int rank = bx & 1;
    const int tid  = threadIdx.x;
    const int wid  = tid >> 5, lane = tid & 31;
    const int g    = lane >> 2, tq = lane & 3;
    const int wm   = (wid >> 1) * 32;   // 4 m-groups of 32 rows
    const int wn   = (wid & 1) * 32;    // 2 n-groups of 32 cols

    // ---- resident weight slice: 64 n-rows x 1024 k halves, XOR-swizzled
    {
        const __half* wsrc = g_Wh + (((size_t)(l * 2 + rank) * HID) + nt * 64) * HID;
        for (int i = tid; i < 8192; i += 256) {
            int n = i >> 7, u = i & 127;
            uint32_t dst = sb + SM_W + (uint32_t)(n * 2048 + ((u >> 3) << 7)
                           + (((u & 7) ^ (n & 7)) << 4));
            cp16(dst, wsrc + (size_t)n * HID + u * 8);
        }
        asm volatile("cp.async.commit_group;" ::: "memory");
        asm volatile("cp.async.wait_group 0;" ::: "memory");
        __syncthreads();
    }

    // ---- per-thread constant addressing ----
    const int rA  = wm + (lane & 15);
    const int h16 = lane >> 4;
    const int sAx = rA & 7;
    const int sBx = (wn + (lane & 15)) & 7;
    const uint32_t aTail = (uint32_t)(rA * 128);
    int aoff[4], boff[4];
    #pragma unroll
    for (int j = 0; j < 4; j++) {
        aoff[j] = ((2 * j + h16) ^ sAx) << 4;
        boff[j] = ((2 * j + h16) ^ sBx) << 4;
    }
    const uint32_t wb0 = sb + SM_W + (uint32_t)((wn + (lane & 15)) * 2048);
    const uint32_t wb1 = wb0 + 16 * 2048;

    // fill geometry: thread -> (row fr, 16B-unit fu), 4 rows per chunk
    const int fr = tid >> 3, fu = tid & 7;
    const uint32_t fTail = (uint32_t)(fr * 128 + ((fu ^ (fr & 7)) << 4));
    const int fGoff = fr * HID + fu * 8;

    float2 bs[4];
    #pragma unroll
    for (int nti = 0; nti < 4; nti++)
        bs[nti] = *(const float2*)&g_bias[l * HID + nt * 64 + wn + nti * 8 + tq * 2];

    const int  fin0    = rank * 64;
    const int  nonfin0 = 64 - fin0;
    const bool fin_w   = (rank == 0) ? (wm < 64) : (wm >= 64);
    float* sP = (float*)(sh + SM_P);
    const uint32_t peer_sp = mapa_u32(sb + SM_P, (uint32_t)(rank ^ 1));

    #pragma unroll 1
    for (int t = 0; t < T_STEPS; t++) {
        // ---- dependency gate (3 warps poll in parallel) ----
        if (wid == 0)               poll_group(l * 32, t, lane);            // own
        else if (wid == 1 && l > 0) poll_group((l - 1) * 32, t + 1, lane);  // up
        else if (wid == 2 && l < 3) poll_group((l + 1) * 32, t - 1, lane);  // WAR
        __syncthreads();

        const __half* src;
        if (rank == 1)   src = g_act[(t & 1) ^ 1] + (size_t)l * BATCH * HID;
        else if (l == 0) src = g_xh + (size_t)t * BATCH * HID;
        else             src = g_act[t & 1] + (size_t)(l - 1) * BATCH * HID;
        const __half* gp0 = src + fGoff;

        // prologue fills: chunk 0 -> buf0, chunk 1 -> buf1
        #pragma unroll
        for (int c0 = 0; c0 < 2; c0++) {
            uint32_t d = sb + SM_AB + (uint32_t)(c0 * ABUF) + fTail;
            const __half* gp = gp0 + c0 * 64;
            cp16(d,         gp);
            cp16(d + 4096,  gp + 32 * HID);
            cp16(d + 8192,  gp + 64 * HID);
            cp16(d + 12288, gp + 96 * HID);
            asm volatile("cp.async.commit_group;" ::: "memory");
        }

        float acc[2][4][4];
        #pragma unroll
        for (int i = 0; i < 2; i++)
            #pragma unroll
            for (int j = 0; j < 4; j++)
                #pragma unroll
                for (int k = 0; k < 4; k++) acc[i][j][k] = 0.0f;

        int b = 0, fb = 2;
        #pragma unroll 1
        for (int ch = 0; ch < 16; ch++) {
            if (ch < 15) asm volatile("cp.async.wait_group 1;" ::: "memory");
            else         asm volatile("cp.async.wait_group 0;" ::: "memory");
            __syncthreads();

            if (ch < 14) {  // refill buf fb with chunk ch+2 (consumed at ch-1)
                uint32_t d = sb + SM_AB + (uint32_t)(fb * ABUF) + fTail;
                const __half* gp = gp0 + (ch + 2) * 64;
                cp16(d,         gp);
                cp16(d + 4096,  gp + 32 * HID);
                cp16(d + 8192,  gp + 64 * HID);
                cp16(d + 12288, gp + 96 * HID);
                asm volatile("cp.async.commit_group;" ::: "memory");
                fb = (fb == 2) ? 0 : fb + 1;
            }

            const uint32_t abA = sb + SM_AB + (uint32_t)(b * ABUF) + aTail;
            const uint32_t kb  = (uint32_t)(ch << 7);
            #pragma unroll
            for (int j = 0; j < 4; j++) {
                uint32_t a0[4], a1[4], b0[4], b1[4];
                ldsm4(a0, abA + aoff[j]);
                ldsm4(a1, abA + 2048 + aoff[j]);
                ldsm4(b0, wb0 + kb + boff[j]);
                ldsm4(b1, wb1 + kb + boff[j]);
                mma16816(acc[0][0], a0, b0[0], b0[2]);
                mma16816(acc[0][1], a0, b0[1], b0[3]);
                mma16816(acc[0][2], a0, b1[0], b1[2]);
                mma16816(acc[0][3], a0, b1[1], b1[3]);
                mma16816(acc[1][0], a1, b0[0], b0[2]);
                mma16816(acc[1][1], a1, b0[1], b0[3]);
                mma16816(acc[1][2], a1, b1[0], b1[2]);
                mma16816(acc[1][3], a1, b1[1], b1[3]);
            }
            b = (b == 2) ? 0 : b + 1;
        }

        // ---- PUSH partial rows to peer's sP (remote write)
        if (!fin_w) {
            #pragma unroll
            for (int mt = 0; mt < 2; mt++) {
                int rr = wm + mt * 16 + g - nonfin0;
                #pragma unroll
                for (int nti = 0; nti < 4; nti++) {
                    int c = wn + nti * 8 + tq * 2;
                    st_dsmem2(peer_sp + (uint32_t)(rr * 68 + c) * 4,
                              acc[mt][nti][0], acc[mt][nti][1]);
                    st_dsmem2(peer_sp + (uint32_t)((rr + 8) * 68 + c) * 4,
                              acc[mt][nti][2], acc[mt][nti][3]);
                }
            }
        }
        asm volatile("barrier.cluster.arrive.aligned;" ::: "memory");
        asm volatile("barrier.cluster.wait.aligned;" ::: "memory");

        // ---- finalize: local sP read + bias + tanh -> act slot t&1 (+ out)
        if (fin_w) {
            __half* actw = g_act[t & 1] + (size_t)l * BATCH * HID;
            #pragma unroll
            for (int mt = 0; mt < 2; mt++) {
                int rg = wm + mt * 16 + g;
                int rr = rg - fin0;
                #pragma unroll
                for (int nti = 0; nti < 4; nti++) {
                    int c = wn + nti * 8 + tq * 2;
                    float2 p0 = *(const float2*)&sP[rr * 68 + c];
                    float2 p1 = *(const float2*)&sP[(rr + 8) * 68 + c];
                    float v0 = tanhf(acc[mt][nti][0] + p0.x + bs[nti].x);
                    float v1 = tanhf(acc[mt][nti][1] + p0.y + bs[nti].y);
                    float v2 = tanhf(acc[mt][nti][2] + p1.x + bs[nti].x);
                    float v3 = tanhf(acc[mt][nti][3] + p1.y + bs[nti].y);
                    int cn = nt * 64 + c;
                    *(__half2*)&actw[(size_t)rg * HID + cn] =
                        __floats2half2_rn(v0, v1);
                    *(__half2*)&actw[(size_t)(rg + 8) * HID + cn] =
                        __floats2half2_rn(v2, v3);
                    if (l == 3) {
                        float* ob = out + (size_t)t * BATCH * HID + cn;
                        *(float2*)&ob[(size_t)rg * HID] = make_float2(v0, v1);
                        *(float2*)&ob[(size_t)(rg + 8) * HID] = make_float2(v2, v3);
                    }
                }
            }
        }

        // ---- publish progress ----
        __syncthreads();
        if (tid == 0) {
            __threadfence();
            atomicExch(&g_flags[bx * 32], (unsigned)(t + 1));
        }
    }
}

// -------------------------------------------------------------- launch ----
extern "C" void kernel_launch(void* const* d_in, const int* in_sizes, int n_in,
                              void* d_out, int out_size)
{
    const float* x   = (const float*)d_in[0];
    const float* Wih = (const float*)d_in[1];
    const float* Whh = (const float*)d_in[2];
    const float* bih = (const float*)d_in[3];
    const float* bhh = (const float*)d_in[4];
    float* out = (float*)d_out;

    cudaFuncSetAttribute(rnn_persistent,
                         cudaFuncAttributeMaxDynamicSharedMemorySize, SMEM_BYTES);

    prep_kernel<<<2048, 256>>>(x, Wih, Whh, bih, bhh);
    rnn_persistent<<<NCTA, 256, SMEM_BYTES>>>(out);
}